// round 5
// baseline (speedup 1.0000x reference)
#include <cuda_runtime.h>
#include <cuda_bf16.h>
#include <cstdint>

// Problem constants
constexpr int B_  = 32;
constexpr int H_  = 12;
constexpr int W_  = 256;
constexpr int C_  = 256;
constexpr int HS_ = 4;            // H / SPLIT
constexpr int N_  = HS_ * W_;     // 1024 flattened spatial
constexpr int FC_ = 96;           // SPLIT * Cf
constexpr int HC_ = 768;          // SPLIT * C
constexpr int P_  = B_ * H_ * W_; // 98304 pixels

// Scratch (device globals)
__device__ __nv_bfloat16 g_xhi[(size_t)P_ * C_];        // 50 MB
__device__ __nv_bfloat16 g_xlo[(size_t)P_ * C_];        // 50 MB
__device__ __nv_bfloat16 g_Wthi[320 * 256];             // [j][k] transposed concat
__device__ __nv_bfloat16 g_Wtlo[320 * 256];
__device__ __nv_bfloat16 g_fhi[(size_t)B_ * N_ * FC_];  // 6.3 MB each
__device__ __nv_bfloat16 g_flo[(size_t)B_ * N_ * FC_];
__device__ __nv_bfloat16 g_ghi[(size_t)B_ * N_ * FC_];
__device__ __nv_bfloat16 g_glo[(size_t)B_ * N_ * FC_];
__device__ float g_s[(size_t)B_ * N_ * N_];             // 134 MB
__device__ __nv_bfloat16 g_beta[(size_t)B_ * N_ * N_];  // 64 MB  [b][n][m]
__device__ __nv_bfloat16 g_hT[(size_t)B_ * HC_ * N_];   // 48 MB  [b][c][n]

// ============================ PTX helpers ==================================
__device__ __forceinline__ uint32_t smem_u32(const void* p) {
    uint32_t a;
    asm("{ .reg .u64 t; cvta.to.shared.u64 t, %1; cvt.u32.u64 %0, t; }"
        : "=r"(a) : "l"(p));
    return a;
}
#define CP16(s, g) \
    asm volatile("cp.async.cg.shared.global [%0], [%1], 16;" \
        :: "r"(s), "l"(g) : "memory")
#define CPCOMMIT() asm volatile("cp.async.commit_group;" ::: "memory")
#define CPWAIT(n)  asm volatile("cp.async.wait_group %0;" :: "n"(n) : "memory")

__device__ __forceinline__ void ldsm_x4(uint32_t& r0, uint32_t& r1,
                                        uint32_t& r2, uint32_t& r3, uint32_t addr) {
    asm volatile("ldmatrix.sync.aligned.m8n8.x4.shared.b16 {%0,%1,%2,%3}, [%4];"
        : "=r"(r0), "=r"(r1), "=r"(r2), "=r"(r3) : "r"(addr));
}
__device__ __forceinline__ void mma_bf16(float* c, const uint32_t* a, const uint32_t* b) {
    asm volatile("mma.sync.aligned.m16n8k16.row.col.f32.bf16.bf16.f32 "
        "{%0,%1,%2,%3}, {%4,%5,%6,%7}, {%8,%9}, {%0,%1,%2,%3};"
        : "+f"(c[0]), "+f"(c[1]), "+f"(c[2]), "+f"(c[3])
        : "r"(a[0]), "r"(a[1]), "r"(a[2]), "r"(a[3]), "r"(b[0]), "r"(b[1]));
}
// smem tile: 64B rows (32 bf16), 4x16B chunks/row, XOR swizzle for ldmatrix
__device__ __forceinline__ uint32_t swz(int r, int c) {
    return (uint32_t)(r * 64 + ((c ^ ((r >> 1) & 3)) << 4));
}
__device__ __forceinline__ void split2(float v, __nv_bfloat16& hi, __nv_bfloat16& lo) {
    hi = __float2bfloat16(v);
    lo = __float2bfloat16(v - __bfloat162float(hi));
}

// ---------------------------------------------------------------------------
// Kernel 0a: split x into bf16 hi/lo
// ---------------------------------------------------------------------------
__global__ __launch_bounds__(256) void k_split_x(const float* __restrict__ x)
{
    size_t gid = (size_t)blockIdx.x * 256 + threadIdx.x;   // float4 index
    float4 v = reinterpret_cast<const float4*>(x)[gid];
    __nv_bfloat16 h0, h1, h2, h3, l0, l1, l2, l3;
    split2(v.x, h0, l0); split2(v.y, h1, l1);
    split2(v.z, h2, l2); split2(v.w, h3, l3);
    uint2 hu, lu;
    reinterpret_cast<__nv_bfloat162*>(&hu)[0] = __nv_bfloat162(h0, h1);
    reinterpret_cast<__nv_bfloat162*>(&hu)[1] = __nv_bfloat162(h2, h3);
    reinterpret_cast<__nv_bfloat162*>(&lu)[0] = __nv_bfloat162(l0, l1);
    reinterpret_cast<__nv_bfloat162*>(&lu)[1] = __nv_bfloat162(l2, l3);
    reinterpret_cast<uint2*>(g_xhi)[gid] = hu;
    reinterpret_cast<uint2*>(g_xlo)[gid] = lu;
}

// ---------------------------------------------------------------------------
// Kernel 0b: build transposed split concat weight Wt[j][k], j in [0,320)
// ---------------------------------------------------------------------------
__global__ __launch_bounds__(256) void k_split_w(
    const float* __restrict__ Wf, const float* __restrict__ Wg,
    const float* __restrict__ Wh)
{
    const int j = blockIdx.x;
    const int k = threadIdx.x;
    float v;
    if (j < 256)      v = Wh[k * 256 + j];
    else if (j < 288) v = Wf[k * 32 + (j - 256)];
    else              v = Wg[k * 32 + (j - 288)];
    __nv_bfloat16 hi, lo;
    split2(v, hi, lo);
    g_Wthi[j * 256 + k] = hi;
    g_Wtlo[j * 256 + k] = lo;
}

// ---------------------------------------------------------------------------
// Kernel 1: projections via 3-pass bf16 HMMA.
// C[P,320] = X[P,256] @ Wt^T. Tile 128x64x32, 8 warps (4m x 2n).
// Epilogue: h tiles transposed in smem -> coalesced g_hT write (no separate
// transpose kernel); f/g written as hi/lo bf16 pairs.
// ---------------------------------------------------------------------------
constexpr int PJ_STAGE = 24576;   // Ah 8K + Al 8K + Bh 4K + Bl 4K
constexpr int PJ_STGS  = 3;
constexpr int TS_ = 136;          // transpose staging row pitch (bf16), 16B-aligned

__global__ __launch_bounds__(256) void k_proj_mma()
{
    extern __shared__ char smem[];
    const uint32_t sbase = smem_u32(smem);
    const int tid  = threadIdx.x;
    const int wid  = tid >> 5;
    const int lane = tid & 31;
    const int wm   = wid & 3;
    const int wn   = wid >> 2;
    const int cBase = blockIdx.x * 64;     // 5 blocks
    const int pBase = blockIdx.y * 128;

    const __nv_bfloat16* gAh = g_xhi + (size_t)pBase * 256;
    const __nv_bfloat16* gAl = g_xlo + (size_t)pBase * 256;
    const __nv_bfloat16* gBh = g_Wthi + (size_t)cBase * 256;
    const __nv_bfloat16* gBl = g_Wtlo + (size_t)cBase * 256;

    const int arow = tid >> 2, ac = tid & 3;
    auto issue = [&](int slot, int kc) {
        const uint32_t st = sbase + slot * PJ_STAGE;
        const int kOff = kc * 32 + ac * 8;
#pragma unroll
        for (int i = 0; i < 2; i++) {
            int idx = i * 256 + tid;
            int r = idx >> 2, c = idx & 3;
            int ko = kc * 32 + c * 8;
            CP16(st + swz(r, c), gAh + (size_t)r * 256 + ko);
            CP16(st + 8192 + swz(r, c), gAl + (size_t)r * 256 + ko);
        }
        if (arow < 64) {
            CP16(st + 16384 + swz(arow, ac), gBh + (size_t)arow * 256 + kOff);
            CP16(st + 20480 + swz(arow, ac), gBl + (size_t)arow * 256 + kOff);
        }
    };

    float acc[2][4][4];
#pragma unroll
    for (int mt = 0; mt < 2; mt++)
#pragma unroll
        for (int nt = 0; nt < 4; nt++)
#pragma unroll
            for (int j = 0; j < 4; j++) acc[mt][nt][j] = 0.f;

    issue(0, 0); CPCOMMIT();
    issue(1, 1); CPCOMMIT();

    for (int kc = 0; kc < 8; kc++) {
        if (kc + 2 < 8) {
            issue((kc + 2) % PJ_STGS, kc + 2); CPCOMMIT();
            CPWAIT(2);
        } else {
            CPWAIT(0);
        }
        __syncthreads();
        const uint32_t st = sbase + (kc % PJ_STGS) * PJ_STAGE;
#pragma unroll
        for (int ks = 0; ks < 2; ks++) {
            uint32_t ah[2][4], al[2][4];
#pragma unroll
            for (int mt = 0; mt < 2; mt++) {
                int row = wm * 32 + mt * 16 + ((lane >> 3) & 1) * 8 + (lane & 7);
                int ch  = ks * 2 + (lane >> 4);
                ldsm_x4(ah[mt][0], ah[mt][1], ah[mt][2], ah[mt][3], st + swz(row, ch));
                ldsm_x4(al[mt][0], al[mt][1], al[mt][2], al[mt][3], st + 8192 + swz(row, ch));
            }
            uint32_t bh[4][2], bl[4][2];
#pragma unroll
            for (int p = 0; p < 2; p++) {
                int row = wn * 32 + p * 16 + (lane >> 4) * 8 + (lane & 7);
                int ch  = ks * 2 + ((lane >> 3) & 1);
                uint32_t r0, r1, r2, r3;
                ldsm_x4(r0, r1, r2, r3, st + 16384 + swz(row, ch));
                bh[2 * p][0] = r0; bh[2 * p][1] = r1;
                bh[2 * p + 1][0] = r2; bh[2 * p + 1][1] = r3;
                ldsm_x4(r0, r1, r2, r3, st + 20480 + swz(row, ch));
                bl[2 * p][0] = r0; bl[2 * p][1] = r1;
                bl[2 * p + 1][0] = r2; bl[2 * p + 1][1] = r3;
            }
#pragma unroll
            for (int mt = 0; mt < 2; mt++)
#pragma unroll
                for (int nt = 0; nt < 4; nt++) {
                    mma_bf16(acc[mt][nt], ah[mt], bh[nt]);
                    mma_bf16(acc[mt][nt], ah[mt], bl[nt]);
                    mma_bf16(acc[mt][nt], al[mt], bh[nt]);
                }
        }
        __syncthreads();
    }

    // Geometry: 128 consecutive pixels = fixed (b, h), 128 consecutive w.
    const int gr = lane >> 2;
    const int qc = (lane & 3) * 2;
    const int bb  = pBase / (H_ * W_);
    const int rem = pBase - bb * (H_ * W_);
    const int hpx = rem >> 8;
    const int w0  = rem & 255;
    const int sg  = hpx >> 2;
    const int hr  = hpx & 3;
    const int n0  = hr * W_ + w0;

    if (cBase < 256) {
        // h path: stage transposed [c=64][n=128] in smem, write g_hT coalesced
        __nv_bfloat16* ts = reinterpret_cast<__nv_bfloat16*>(smem);
#pragma unroll
        for (int mt = 0; mt < 2; mt++)
#pragma unroll
            for (int rr = 0; rr < 2; rr++) {
                int nl = wm * 32 + mt * 16 + rr * 8 + gr;   // pixel within tile
#pragma unroll
                for (int nt = 0; nt < 4; nt++) {
                    int cl = wn * 32 + nt * 8 + qc;          // channel within tile
                    ts[cl * TS_ + nl]       = __float2bfloat16(acc[mt][nt][rr * 2 + 0]);
                    ts[(cl + 1) * TS_ + nl] = __float2bfloat16(acc[mt][nt][rr * 2 + 1]);
                }
            }
        __syncthreads();
        const size_t hTrow0 = ((size_t)bb * HC_ + sg * 256 + cBase) * N_ + n0;
#pragma unroll
        for (int i = 0; i < 4; i++) {
            int idx = i * 256 + tid;
            int r = idx >> 4, u = idx & 15;
            uint4 v = *reinterpret_cast<const uint4*>(&ts[r * TS_ + u * 8]);
            *reinterpret_cast<uint4*>(&g_hT[hTrow0 + (size_t)r * N_ + u * 8]) = v;
        }
    } else {
        // f/g path: hi/lo split scatter
#pragma unroll
        for (int mt = 0; mt < 2; mt++)
#pragma unroll
            for (int rr = 0; rr < 2; rr++) {
                int nl = wm * 32 + mt * 16 + rr * 8 + gr;
                int n  = n0 + nl;
                size_t base = ((size_t)bb * N_ + n) * FC_ + sg * 32;
#pragma unroll
                for (int nt = 0; nt < 4; nt++) {
                    int j = cBase + wn * 32 + nt * 8 + qc;   // 256..319
                    float v0 = acc[mt][nt][rr * 2 + 0];
                    float v1 = acc[mt][nt][rr * 2 + 1];
                    __nv_bfloat16 h0, h1, l0, l1;
                    split2(v0, h0, l0); split2(v1, h1, l1);
                    __nv_bfloat162 hv(h0, h1), lv(l0, l1);
                    if (j < 288) {
                        size_t idx = base + (j - 256);
                        *reinterpret_cast<__nv_bfloat162*>(&g_fhi[idx]) = hv;
                        *reinterpret_cast<__nv_bfloat162*>(&g_flo[idx]) = lv;
                    } else {
                        size_t idx = base + (j - 288);
                        *reinterpret_cast<__nv_bfloat162*>(&g_ghi[idx]) = hv;
                        *reinterpret_cast<__nv_bfloat162*>(&g_glo[idx]) = lv;
                    }
                }
            }
    }
}

// ---------------------------------------------------------------------------
// Kernel 2: s[b] = g_fl[b] @ f_fl[b]^T via 3-pass bf16 HMMA.
// Tile 128x128, K=96 one-shot (3 subtiles of 32). 8 warps (4m x 2n).
// ---------------------------------------------------------------------------
constexpr int SC_BUF = 24576;   // one operand buffer: 3 subtiles x 8KB

__global__ __launch_bounds__(256) void k_score_mma()
{
    extern __shared__ char smem[];
    const uint32_t sbase = smem_u32(smem);
    const int tid  = threadIdx.x;
    const int wid  = tid >> 5;
    const int lane = tid & 31;
    const int wm   = wid & 3;
    const int wn   = wid >> 2;
    const int b     = blockIdx.z;
    const int mBase = blockIdx.x * 128;   // cols of s (f index)
    const int nBase = blockIdx.y * 128;   // rows of s (g index)

    const __nv_bfloat16* srcs[4] = {
        g_ghi + ((size_t)b * N_ + nBase) * FC_,
        g_glo + ((size_t)b * N_ + nBase) * FC_,
        g_fhi + ((size_t)b * N_ + mBase) * FC_,
        g_flo + ((size_t)b * N_ + mBase) * FC_ };

#pragma unroll
    for (int bf = 0; bf < 4; bf++) {
        const __nv_bfloat16* src = srcs[bf];
        const uint32_t bufS = sbase + bf * SC_BUF;
#pragma unroll
        for (int t = 0; t < 3; t++)
#pragma unroll
            for (int i = 0; i < 2; i++) {
                int idx = i * 256 + tid;
                int r = idx >> 2, c = idx & 3;
                CP16(bufS + t * 8192 + swz(r, c),
                     src + (size_t)r * FC_ + t * 32 + c * 8);
            }
    }
    CPCOMMIT(); CPWAIT(0);
    __syncthreads();

    float acc[2][8][4];
#pragma unroll
    for (int mt = 0; mt < 2; mt++)
#pragma unroll
        for (int nt = 0; nt < 8; nt++)
#pragma unroll
            for (int j = 0; j < 4; j++) acc[mt][nt][j] = 0.f;

    const uint32_t AhS = sbase, AlS = sbase + SC_BUF;
    const uint32_t BhS = sbase + 2 * SC_BUF, BlS = sbase + 3 * SC_BUF;

#pragma unroll
    for (int t = 0; t < 3; t++) {
#pragma unroll
        for (int ks = 0; ks < 2; ks++) {
            uint32_t ah[2][4], al[2][4];
#pragma unroll
            for (int mt = 0; mt < 2; mt++) {
                int row = wm * 32 + mt * 16 + ((lane >> 3) & 1) * 8 + (lane & 7);
                int ch  = ks * 2 + (lane >> 4);
                ldsm_x4(ah[mt][0], ah[mt][1], ah[mt][2], ah[mt][3],
                        AhS + t * 8192 + swz(row, ch));
                ldsm_x4(al[mt][0], al[mt][1], al[mt][2], al[mt][3],
                        AlS + t * 8192 + swz(row, ch));
            }
            uint32_t bh[8][2], bl[8][2];
#pragma unroll
            for (int p = 0; p < 4; p++) {
                int row = wn * 64 + p * 16 + (lane >> 4) * 8 + (lane & 7);
                int ch  = ks * 2 + ((lane >> 3) & 1);
                uint32_t r0, r1, r2, r3;
                ldsm_x4(r0, r1, r2, r3, BhS + t * 8192 + swz(row, ch));
                bh[2 * p][0] = r0; bh[2 * p][1] = r1;
                bh[2 * p + 1][0] = r2; bh[2 * p + 1][1] = r3;
                ldsm_x4(r0, r1, r2, r3, BlS + t * 8192 + swz(row, ch));
                bl[2 * p][0] = r0; bl[2 * p][1] = r1;
                bl[2 * p + 1][0] = r2; bl[2 * p + 1][1] = r3;
            }
#pragma unroll
            for (int mt = 0; mt < 2; mt++)
#pragma unroll
                for (int nt = 0; nt < 8; nt++) {
                    mma_bf16(acc[mt][nt], ah[mt], bh[nt]);
                    mma_bf16(acc[mt][nt], ah[mt], bl[nt]);
                    mma_bf16(acc[mt][nt], al[mt], bh[nt]);
                }
        }
    }

    float* sp = g_s + (size_t)b * N_ * N_;
    const int gr = lane >> 2;
    const int qc = (lane & 3) * 2;
#pragma unroll
    for (int mt = 0; mt < 2; mt++)
#pragma unroll
        for (int rr = 0; rr < 2; rr++) {
            int n = nBase + wm * 32 + mt * 16 + rr * 8 + gr;
#pragma unroll
            for (int nt = 0; nt < 8; nt++) {
                int m = mBase + wn * 64 + nt * 8 + qc;
                float2 v = make_float2(acc[mt][nt][rr * 2], acc[mt][nt][rr * 2 + 1]);
                *reinterpret_cast<float2*>(&sp[(size_t)n * N_ + m]) = v;
            }
        }
}

// ---------------------------------------------------------------------------
// Kernel 3: row softmax (float4 + shuffle reductions); writes bf16 beta
// ---------------------------------------------------------------------------
__global__ __launch_bounds__(256) void k_softmax()
{
    const size_t row = blockIdx.x;
    const float4* sp4 = reinterpret_cast<const float4*>(g_s + row * N_);
    const int tid = threadIdx.x;
    const int lane = tid & 31, warp = tid >> 5;
    __shared__ float red[8];

    float4 v = sp4[tid];
    float m = fmaxf(fmaxf(v.x, v.y), fmaxf(v.z, v.w));
#pragma unroll
    for (int o = 16; o > 0; o >>= 1)
        m = fmaxf(m, __shfl_xor_sync(0xFFFFFFFF, m, o));
    if (lane == 0) red[warp] = m;
    __syncthreads();
    m = red[lane & 7];
#pragma unroll
    for (int o = 4; o > 0; o >>= 1)
        m = fmaxf(m, __shfl_xor_sync(0xFFFFFFFF, m, o));

    float e0 = __expf(v.x - m), e1 = __expf(v.y - m);
    float e2 = __expf(v.z - m), e3 = __expf(v.w - m);
    float s = e0 + e1 + e2 + e3;
#pragma unroll
    for (int o = 16; o > 0; o >>= 1)
        s += __shfl_xor_sync(0xFFFFFFFF, s, o);
    __syncthreads();
    if (lane == 0) red[warp] = s;
    __syncthreads();
    s = red[lane & 7];
#pragma unroll
    for (int o = 4; o > 0; o >>= 1)
        s += __shfl_xor_sync(0xFFFFFFFF, s, o);
    float inv = 1.0f / s;

    uint2 pk;
    reinterpret_cast<__nv_bfloat162*>(&pk)[0] =
        __nv_bfloat162(__float2bfloat16(e0 * inv), __float2bfloat16(e1 * inv));
    reinterpret_cast<__nv_bfloat162*>(&pk)[1] =
        __nv_bfloat162(__float2bfloat16(e2 * inv), __float2bfloat16(e3 * inv));
    reinterpret_cast<uint2*>(g_beta + row * N_)[tid] = pk;
}

// ---------------------------------------------------------------------------
// Kernel 4: bf16 HMMA GEMM  o[b] = beta[b] @ h_fl[b]  (M=1024, N=768, K=1024)
// CTA tile 256x256x32, 512 threads (16 warps 4m x 4n), warp tile 64x64.
// 3-stage cp.async pipeline. Epilogue fuses hw_recover + gamma*o + x.
// ---------------------------------------------------------------------------
constexpr int BK_    = 32;
constexpr int NK_    = N_ / BK_;   // 32 k-chunks
constexpr int OSTAGE = 32768;      // 16KB A + 16KB B per stage
constexpr int OSTGS  = 3;

__global__ __launch_bounds__(512, 1) void k_o_mma(
    const float* __restrict__ x, const float* __restrict__ gammaP,
    float* __restrict__ out)
{
    extern __shared__ char smem[];
    const uint32_t sbase = smem_u32(smem);

    const int tid  = threadIdx.x;
    const int wid  = tid >> 5;
    const int lane = tid & 31;
    const int wm   = wid & 3;      // 4 m-warps * 64 rows
    const int wn   = wid >> 2;     // 4 n-warps * 64 cols
    const int b     = blockIdx.z;
    const int mBase = blockIdx.y * 256;
    const int cBase = blockIdx.x * 256;

    const __nv_bfloat16* gA = g_beta + ((size_t)b * N_ + mBase) * N_;  // [256][1024]
    const __nv_bfloat16* gB = g_hT  + ((size_t)b * HC_ + cBase) * N_;  // [256][1024]

    auto issue = [&](int slot, int kc) {
        const uint32_t aS = sbase + slot * OSTAGE;
        const uint32_t bS = aS + 16384;
#pragma unroll
        for (int i = 0; i < 2; i++) {
            int idx = i * 512 + tid;
            int r = idx >> 2, c = idx & 3;
            int ko = kc * BK_ + c * 8;
            CP16(aS + swz(r, c), gA + (size_t)r * N_ + ko);
            CP16(bS + swz(r, c), gB + (size_t)r * N_ + ko);
        }
    };

    float acc[4][8][4];
#pragma unroll
    for (int mt = 0; mt < 4; mt++)
#pragma unroll
        for (int nt = 0; nt < 8; nt++)
#pragma unroll
            for (int j = 0; j < 4; j++) acc[mt][nt][j] = 0.f;

    issue(0, 0); CPCOMMIT();
    issue(1, 1); CPCOMMIT();

    for (int kc = 0; kc < NK_; kc++) {
        if (kc + 2 < NK_) {
            issue((kc + 2) % OSTGS, kc + 2); CPCOMMIT();
            CPWAIT(2);
        } else {
            CPWAIT(0);
        }
        __syncthreads();

        const uint32_t aS = sbase + (kc % OSTGS) * OSTAGE;
        const uint32_t bS = aS + 16384;
#pragma unroll
        for (int ks = 0; ks < 2; ks++) {
            uint32_t afr[4][4];
#pragma unroll
            for (int mt = 0; mt < 4; mt++) {
                int row = wm * 64 + mt * 16 + ((lane >> 3) & 1) * 8 + (lane & 7);
                int ch  = ks * 2 + (lane >> 4);
                ldsm_x4(afr[mt][0], afr[mt][1], afr[mt][2], afr[mt][3],
                        aS + swz(row, ch));
            }
            uint32_t bfr[8][2];
#pragma unroll
            for (int p = 0; p < 4; p++) {
                int row = wn * 64 + p * 16 + (lane >> 4) * 8 + (lane & 7);
                int ch  = ks * 2 + ((lane >> 3) & 1);
                uint32_t r0, r1, r2, r3;
                ldsm_x4(r0, r1, r2, r3, bS + swz(row, ch));
                bfr[2 * p][0] = r0; bfr[2 * p][1] = r1;
                bfr[2 * p + 1][0] = r2; bfr[2 * p + 1][1] = r3;
            }
#pragma unroll
            for (int mt = 0; mt < 4; mt++)
#pragma unroll
                for (int nt = 0; nt < 8; nt++)
                    mma_bf16(acc[mt][nt], afr[mt], bfr[nt]);
        }
        __syncthreads();
    }

    const float gamma = __ldg(gammaP);
    const int gr = lane >> 2;
    const int qc = (lane & 3) * 2;
#pragma unroll
    for (int mt = 0; mt < 4; mt++) {
#pragma unroll
        for (int rr = 0; rr < 2; rr++) {
            int m    = mBase + wm * 64 + mt * 16 + rr * 8 + gr;
            int hr   = m >> 8;
            int wpix = m & 255;
#pragma unroll
            for (int nt = 0; nt < 8; nt++) {
                int cg = cBase + wn * 64 + nt * 8 + qc;
                int sg = cg >> 8;
                int ch = cg & 255;
                int hh = sg * HS_ + hr;
                size_t idx = (((size_t)b * H_ + hh) * W_ + wpix) * C_ + ch;
                float2 xv = *reinterpret_cast<const float2*>(x + idx);
                float2 o;
                o.x = fmaf(gamma, acc[mt][nt][rr * 2 + 0], xv.x);
                o.y = fmaf(gamma, acc[mt][nt][rr * 2 + 1], xv.y);
                *reinterpret_cast<float2*>(out + idx) = o;
            }
        }
    }
}

// ---------------------------------------------------------------------------
extern "C" void kernel_launch(void* const* d_in, const int* in_sizes, int n_in,
                              void* d_out, int out_size)
{
    const float* x     = (const float*)d_in[0];
    const float* Wf    = (const float*)d_in[1];
    const float* Wg    = (const float*)d_in[2];
    const float* Wh    = (const float*)d_in[3];
    const float* gamma = (const float*)d_in[4];
    float* out = (float*)d_out;

    static bool attrSet = false;
    if (!attrSet) {
        cudaFuncSetAttribute(k_proj_mma, cudaFuncAttributeMaxDynamicSharedMemorySize,
                             PJ_STGS * PJ_STAGE);
        cudaFuncSetAttribute(k_score_mma, cudaFuncAttributeMaxDynamicSharedMemorySize,
                             4 * SC_BUF);
        cudaFuncSetAttribute(k_o_mma, cudaFuncAttributeMaxDynamicSharedMemorySize,
                             OSTGS * OSTAGE);
        attrSet = true;
    }

    k_split_x    <<<P_ * C_ / 4 / 256, 256>>>(x);
    k_split_w    <<<320, 256>>>(Wf, Wg, Wh);
    k_proj_mma   <<<dim3(5, P_ / 128), 256, PJ_STGS * PJ_STAGE>>>();
    k_score_mma  <<<dim3(N_ / 128, N_ / 128, B_), 256, 4 * SC_BUF>>>();
    k_softmax    <<<dim3(B_ * N_), 256>>>();
    k_o_mma      <<<dim3(HC_ / 256, N_ / 256, B_), 512,
                    OSTGS * OSTAGE>>>(x, gamma, out);
}

// round 6
// speedup vs baseline: 1.7846x; 1.7846x over previous
#include <cuda_runtime.h>
#include <cuda_bf16.h>
#include <cstdint>

// Problem constants
constexpr int B_  = 32;
constexpr int H_  = 12;
constexpr int W_  = 256;
constexpr int C_  = 256;
constexpr int HS_ = 4;            // H / SPLIT
constexpr int N_  = HS_ * W_;     // 1024 flattened spatial
constexpr int FC_ = 96;           // SPLIT * Cf
constexpr int HC_ = 768;          // SPLIT * C
constexpr int P_  = B_ * H_ * W_; // 98304 pixels

// Scratch (device globals)
__device__ __nv_bfloat16 g_xhi[(size_t)P_ * C_];        // 50 MB
__device__ __nv_bfloat16 g_xlo[(size_t)P_ * C_];        // 50 MB
__device__ __nv_bfloat16 g_Wthi[320 * 256];             // [j][k] transposed concat
__device__ __nv_bfloat16 g_Wtlo[320 * 256];
__device__ __nv_bfloat16 g_fhi[(size_t)B_ * N_ * FC_];  // 6.3 MB each
__device__ __nv_bfloat16 g_flo[(size_t)B_ * N_ * FC_];
__device__ __nv_bfloat16 g_ghi[(size_t)B_ * N_ * FC_];
__device__ __nv_bfloat16 g_glo[(size_t)B_ * N_ * FC_];
__device__ float g_s[(size_t)B_ * N_ * N_];             // 134 MB
__device__ __nv_bfloat16 g_beta[(size_t)B_ * N_ * N_];  // 64 MB  [b][n][m]
__device__ __nv_bfloat16 g_hT[(size_t)B_ * HC_ * N_];   // 48 MB  [b][c][n]

// ============================ PTX helpers ==================================
__device__ __forceinline__ uint32_t smem_u32(const void* p) {
    uint32_t a;
    asm("{ .reg .u64 t; cvta.to.shared.u64 t, %1; cvt.u32.u64 %0, t; }"
        : "=r"(a) : "l"(p));
    return a;
}
#define CP16(s, g) \
    asm volatile("cp.async.cg.shared.global [%0], [%1], 16;" \
        :: "r"(s), "l"(g) : "memory")
#define CPCOMMIT() asm volatile("cp.async.commit_group;" ::: "memory")
#define CPWAIT(n)  asm volatile("cp.async.wait_group %0;" :: "n"(n) : "memory")

__device__ __forceinline__ void ldsm_x4(uint32_t& r0, uint32_t& r1,
                                        uint32_t& r2, uint32_t& r3, uint32_t addr) {
    asm volatile("ldmatrix.sync.aligned.m8n8.x4.shared.b16 {%0,%1,%2,%3}, [%4];"
        : "=r"(r0), "=r"(r1), "=r"(r2), "=r"(r3) : "r"(addr));
}
__device__ __forceinline__ void mma_bf16(float* c, const uint32_t* a, const uint32_t* b) {
    asm volatile("mma.sync.aligned.m16n8k16.row.col.f32.bf16.bf16.f32 "
        "{%0,%1,%2,%3}, {%4,%5,%6,%7}, {%8,%9}, {%0,%1,%2,%3};"
        : "+f"(c[0]), "+f"(c[1]), "+f"(c[2]), "+f"(c[3])
        : "r"(a[0]), "r"(a[1]), "r"(a[2]), "r"(a[3]), "r"(b[0]), "r"(b[1]));
}
// smem tile: 64B rows (32 bf16), 4x16B chunks/row, XOR swizzle for ldmatrix
__device__ __forceinline__ uint32_t swz(int r, int c) {
    return (uint32_t)(r * 64 + ((c ^ ((r >> 1) & 3)) << 4));
}
__device__ __forceinline__ void split2(float v, __nv_bfloat16& hi, __nv_bfloat16& lo) {
    hi = __float2bfloat16(v);
    lo = __float2bfloat16(v - __bfloat162float(hi));
}

// ---------------------------------------------------------------------------
// Kernel 0a: split x into bf16 hi/lo
// ---------------------------------------------------------------------------
__global__ __launch_bounds__(256) void k_split_x(const float* __restrict__ x)
{
    size_t gid = (size_t)blockIdx.x * 256 + threadIdx.x;   // float4 index
    float4 v = reinterpret_cast<const float4*>(x)[gid];
    __nv_bfloat16 h0, h1, h2, h3, l0, l1, l2, l3;
    split2(v.x, h0, l0); split2(v.y, h1, l1);
    split2(v.z, h2, l2); split2(v.w, h3, l3);
    uint2 hu, lu;
    reinterpret_cast<__nv_bfloat162*>(&hu)[0] = __nv_bfloat162(h0, h1);
    reinterpret_cast<__nv_bfloat162*>(&hu)[1] = __nv_bfloat162(h2, h3);
    reinterpret_cast<__nv_bfloat162*>(&lu)[0] = __nv_bfloat162(l0, l1);
    reinterpret_cast<__nv_bfloat162*>(&lu)[1] = __nv_bfloat162(l2, l3);
    reinterpret_cast<uint2*>(g_xhi)[gid] = hu;
    reinterpret_cast<uint2*>(g_xlo)[gid] = lu;
}

// ---------------------------------------------------------------------------
// Kernel 0b: build transposed split concat weight Wt[j][k], j in [0,320)
// ---------------------------------------------------------------------------
__global__ __launch_bounds__(256) void k_split_w(
    const float* __restrict__ Wf, const float* __restrict__ Wg,
    const float* __restrict__ Wh)
{
    const int j = blockIdx.x;
    const int k = threadIdx.x;
    float v;
    if (j < 256)      v = Wh[k * 256 + j];
    else if (j < 288) v = Wf[k * 32 + (j - 256)];
    else              v = Wg[k * 32 + (j - 288)];
    __nv_bfloat16 hi, lo;
    split2(v, hi, lo);
    g_Wthi[j * 256 + k] = hi;
    g_Wtlo[j * 256 + k] = lo;
}

// ---------------------------------------------------------------------------
// Kernel 1: projections via 3-pass bf16 HMMA.
// C[P,320] = X[P,256] @ Wt^T. Tile 128x64x32, 8 warps (4m x 2n).
// Epilogue: h tiles transposed in smem -> coalesced g_hT write; f/g written
// as hi/lo bf16 pairs.
// ---------------------------------------------------------------------------
constexpr int PJ_STAGE = 24576;   // Ah 8K + Al 8K + Bh 4K + Bl 4K
constexpr int PJ_STGS  = 3;
constexpr int TS_ = 136;          // transpose staging row pitch (bf16), 16B-aligned

__global__ __launch_bounds__(256) void k_proj_mma()
{
    extern __shared__ char smem[];
    const uint32_t sbase = smem_u32(smem);
    const int tid  = threadIdx.x;
    const int wid  = tid >> 5;
    const int lane = tid & 31;
    const int wm   = wid & 3;
    const int wn   = wid >> 2;
    const int cBase = blockIdx.x * 64;     // 5 blocks
    const int pBase = blockIdx.y * 128;

    const __nv_bfloat16* gAh = g_xhi + (size_t)pBase * 256;
    const __nv_bfloat16* gAl = g_xlo + (size_t)pBase * 256;
    const __nv_bfloat16* gBh = g_Wthi + (size_t)cBase * 256;
    const __nv_bfloat16* gBl = g_Wtlo + (size_t)cBase * 256;

    const int arow = tid >> 2, ac = tid & 3;
    auto issue = [&](int slot, int kc) {
        const uint32_t st = sbase + slot * PJ_STAGE;
        const int kOff = kc * 32 + ac * 8;
#pragma unroll
        for (int i = 0; i < 2; i++) {
            int idx = i * 256 + tid;
            int r = idx >> 2, c = idx & 3;
            int ko = kc * 32 + c * 8;
            CP16(st + swz(r, c), gAh + (size_t)r * 256 + ko);
            CP16(st + 8192 + swz(r, c), gAl + (size_t)r * 256 + ko);
        }
        if (arow < 64) {
            CP16(st + 16384 + swz(arow, ac), gBh + (size_t)arow * 256 + kOff);
            CP16(st + 20480 + swz(arow, ac), gBl + (size_t)arow * 256 + kOff);
        }
    };

    float acc[2][4][4];
#pragma unroll
    for (int mt = 0; mt < 2; mt++)
#pragma unroll
        for (int nt = 0; nt < 4; nt++)
#pragma unroll
            for (int j = 0; j < 4; j++) acc[mt][nt][j] = 0.f;

    issue(0, 0); CPCOMMIT();
    issue(1, 1); CPCOMMIT();

    for (int kc = 0; kc < 8; kc++) {
        if (kc + 2 < 8) {
            issue((kc + 2) % PJ_STGS, kc + 2); CPCOMMIT();
            CPWAIT(2);
        } else {
            CPWAIT(0);
        }
        __syncthreads();
        const uint32_t st = sbase + (kc % PJ_STGS) * PJ_STAGE;
#pragma unroll
        for (int ks = 0; ks < 2; ks++) {
            uint32_t ah[2][4], al[2][4];
#pragma unroll
            for (int mt = 0; mt < 2; mt++) {
                int row = wm * 32 + mt * 16 + ((lane >> 3) & 1) * 8 + (lane & 7);
                int ch  = ks * 2 + (lane >> 4);
                ldsm_x4(ah[mt][0], ah[mt][1], ah[mt][2], ah[mt][3], st + swz(row, ch));
                ldsm_x4(al[mt][0], al[mt][1], al[mt][2], al[mt][3], st + 8192 + swz(row, ch));
            }
            uint32_t bh[4][2], bl[4][2];
#pragma unroll
            for (int p = 0; p < 2; p++) {
                int row = wn * 32 + p * 16 + (lane >> 4) * 8 + (lane & 7);
                int ch  = ks * 2 + ((lane >> 3) & 1);
                uint32_t r0, r1, r2, r3;
                ldsm_x4(r0, r1, r2, r3, st + 16384 + swz(row, ch));
                bh[2 * p][0] = r0; bh[2 * p][1] = r1;
                bh[2 * p + 1][0] = r2; bh[2 * p + 1][1] = r3;
                ldsm_x4(r0, r1, r2, r3, st + 20480 + swz(row, ch));
                bl[2 * p][0] = r0; bl[2 * p][1] = r1;
                bl[2 * p + 1][0] = r2; bl[2 * p + 1][1] = r3;
            }
#pragma unroll
            for (int mt = 0; mt < 2; mt++)
#pragma unroll
                for (int nt = 0; nt < 4; nt++) {
                    mma_bf16(acc[mt][nt], ah[mt], bh[nt]);
                    mma_bf16(acc[mt][nt], ah[mt], bl[nt]);
                    mma_bf16(acc[mt][nt], al[mt], bh[nt]);
                }
        }
        __syncthreads();
    }

    // Geometry: 128 consecutive pixels = fixed (b, h), 128 consecutive w.
    const int gr = lane >> 2;
    const int qc = (lane & 3) * 2;
    const int bb  = pBase / (H_ * W_);
    const int rem = pBase - bb * (H_ * W_);
    const int hpx = rem >> 8;
    const int w0  = rem & 255;
    const int sg  = hpx >> 2;
    const int hr  = hpx & 3;
    const int n0  = hr * W_ + w0;

    if (cBase < 256) {
        // h path: stage transposed [c=64][n=128] in smem, write g_hT coalesced
        __nv_bfloat16* ts = reinterpret_cast<__nv_bfloat16*>(smem);
#pragma unroll
        for (int mt = 0; mt < 2; mt++)
#pragma unroll
            for (int rr = 0; rr < 2; rr++) {
                int nl = wm * 32 + mt * 16 + rr * 8 + gr;   // pixel within tile
#pragma unroll
                for (int nt = 0; nt < 4; nt++) {
                    int cl = wn * 32 + nt * 8 + qc;          // channel within tile
                    ts[cl * TS_ + nl]       = __float2bfloat16(acc[mt][nt][rr * 2 + 0]);
                    ts[(cl + 1) * TS_ + nl] = __float2bfloat16(acc[mt][nt][rr * 2 + 1]);
                }
            }
        __syncthreads();
        const size_t hTrow0 = ((size_t)bb * HC_ + sg * 256 + cBase) * N_ + n0;
#pragma unroll
        for (int i = 0; i < 4; i++) {
            int idx = i * 256 + tid;
            int r = idx >> 4, u = idx & 15;
            uint4 v = *reinterpret_cast<const uint4*>(&ts[r * TS_ + u * 8]);
            *reinterpret_cast<uint4*>(&g_hT[hTrow0 + (size_t)r * N_ + u * 8]) = v;
        }
    } else {
        // f/g path: hi/lo split scatter
#pragma unroll
        for (int mt = 0; mt < 2; mt++)
#pragma unroll
            for (int rr = 0; rr < 2; rr++) {
                int nl = wm * 32 + mt * 16 + rr * 8 + gr;
                int n  = n0 + nl;
                size_t base = ((size_t)bb * N_ + n) * FC_ + sg * 32;
#pragma unroll
                for (int nt = 0; nt < 4; nt++) {
                    int j = cBase + wn * 32 + nt * 8 + qc;   // 256..319
                    float v0 = acc[mt][nt][rr * 2 + 0];
                    float v1 = acc[mt][nt][rr * 2 + 1];
                    __nv_bfloat16 h0, h1, l0, l1;
                    split2(v0, h0, l0); split2(v1, h1, l1);
                    __nv_bfloat162 hv(h0, h1), lv(l0, l1);
                    if (j < 288) {
                        size_t idx = base + (j - 256);
                        *reinterpret_cast<__nv_bfloat162*>(&g_fhi[idx]) = hv;
                        *reinterpret_cast<__nv_bfloat162*>(&g_flo[idx]) = lv;
                    } else {
                        size_t idx = base + (j - 288);
                        *reinterpret_cast<__nv_bfloat162*>(&g_ghi[idx]) = hv;
                        *reinterpret_cast<__nv_bfloat162*>(&g_glo[idx]) = lv;
                    }
                }
            }
    }
}

// ---------------------------------------------------------------------------
// Kernel 2: s[b] = g_fl[b] @ f_fl[b]^T via 3-pass bf16 HMMA.
// Tile 128x128, K=96 one-shot (3 subtiles of 32). 8 warps (4m x 2n).
// ---------------------------------------------------------------------------
constexpr int SC_BUF = 24576;   // one operand buffer: 3 subtiles x 8KB

__global__ __launch_bounds__(256) void k_score_mma()
{
    extern __shared__ char smem[];
    const uint32_t sbase = smem_u32(smem);
    const int tid  = threadIdx.x;
    const int wid  = tid >> 5;
    const int lane = tid & 31;
    const int wm   = wid & 3;
    const int wn   = wid >> 2;
    const int b     = blockIdx.z;
    const int mBase = blockIdx.x * 128;   // cols of s (f index)
    const int nBase = blockIdx.y * 128;   // rows of s (g index)

    const __nv_bfloat16* srcs[4] = {
        g_ghi + ((size_t)b * N_ + nBase) * FC_,
        g_glo + ((size_t)b * N_ + nBase) * FC_,
        g_fhi + ((size_t)b * N_ + mBase) * FC_,
        g_flo + ((size_t)b * N_ + mBase) * FC_ };

#pragma unroll
    for (int bf = 0; bf < 4; bf++) {
        const __nv_bfloat16* src = srcs[bf];
        const uint32_t bufS = sbase + bf * SC_BUF;
#pragma unroll
        for (int t = 0; t < 3; t++)
#pragma unroll
            for (int i = 0; i < 2; i++) {
                int idx = i * 256 + tid;
                int r = idx >> 2, c = idx & 3;
                CP16(bufS + t * 8192 + swz(r, c),
                     src + (size_t)r * FC_ + t * 32 + c * 8);
            }
    }
    CPCOMMIT(); CPWAIT(0);
    __syncthreads();

    float acc[2][8][4];
#pragma unroll
    for (int mt = 0; mt < 2; mt++)
#pragma unroll
        for (int nt = 0; nt < 8; nt++)
#pragma unroll
            for (int j = 0; j < 4; j++) acc[mt][nt][j] = 0.f;

    const uint32_t AhS = sbase, AlS = sbase + SC_BUF;
    const uint32_t BhS = sbase + 2 * SC_BUF, BlS = sbase + 3 * SC_BUF;

#pragma unroll
    for (int t = 0; t < 3; t++) {
#pragma unroll
        for (int ks = 0; ks < 2; ks++) {
            uint32_t ah[2][4], al[2][4];
#pragma unroll
            for (int mt = 0; mt < 2; mt++) {
                int row = wm * 32 + mt * 16 + ((lane >> 3) & 1) * 8 + (lane & 7);
                int ch  = ks * 2 + (lane >> 4);
                ldsm_x4(ah[mt][0], ah[mt][1], ah[mt][2], ah[mt][3],
                        AhS + t * 8192 + swz(row, ch));
                ldsm_x4(al[mt][0], al[mt][1], al[mt][2], al[mt][3],
                        AlS + t * 8192 + swz(row, ch));
            }
            uint32_t bh[8][2], bl[8][2];
#pragma unroll
            for (int p = 0; p < 4; p++) {
                int row = wn * 64 + p * 16 + (lane >> 4) * 8 + (lane & 7);
                int ch  = ks * 2 + ((lane >> 3) & 1);
                uint32_t r0, r1, r2, r3;
                ldsm_x4(r0, r1, r2, r3, BhS + t * 8192 + swz(row, ch));
                bh[2 * p][0] = r0; bh[2 * p][1] = r1;
                bh[2 * p + 1][0] = r2; bh[2 * p + 1][1] = r3;
                ldsm_x4(r0, r1, r2, r3, BlS + t * 8192 + swz(row, ch));
                bl[2 * p][0] = r0; bl[2 * p][1] = r1;
                bl[2 * p + 1][0] = r2; bl[2 * p + 1][1] = r3;
            }
#pragma unroll
            for (int mt = 0; mt < 2; mt++)
#pragma unroll
                for (int nt = 0; nt < 8; nt++) {
                    mma_bf16(acc[mt][nt], ah[mt], bh[nt]);
                    mma_bf16(acc[mt][nt], ah[mt], bl[nt]);
                    mma_bf16(acc[mt][nt], al[mt], bh[nt]);
                }
        }
    }

    float* sp = g_s + (size_t)b * N_ * N_;
    const int gr = lane >> 2;
    const int qc = (lane & 3) * 2;
#pragma unroll
    for (int mt = 0; mt < 2; mt++)
#pragma unroll
        for (int rr = 0; rr < 2; rr++) {
            int n = nBase + wm * 32 + mt * 16 + rr * 8 + gr;
#pragma unroll
            for (int nt = 0; nt < 8; nt++) {
                int m = mBase + wn * 64 + nt * 8 + qc;
                float2 v = make_float2(acc[mt][nt][rr * 2], acc[mt][nt][rr * 2 + 1]);
                *reinterpret_cast<float2*>(&sp[(size_t)n * N_ + m]) = v;
            }
        }
}

// ---------------------------------------------------------------------------
// Kernel 3: row softmax (float4 + shuffle reductions); writes bf16 beta
// ---------------------------------------------------------------------------
__global__ __launch_bounds__(256) void k_softmax()
{
    const size_t row = blockIdx.x;
    const float4* sp4 = reinterpret_cast<const float4*>(g_s + row * N_);
    const int tid = threadIdx.x;
    const int lane = tid & 31, warp = tid >> 5;
    __shared__ float red[8];

    float4 v = sp4[tid];
    float m = fmaxf(fmaxf(v.x, v.y), fmaxf(v.z, v.w));
#pragma unroll
    for (int o = 16; o > 0; o >>= 1)
        m = fmaxf(m, __shfl_xor_sync(0xFFFFFFFF, m, o));
    if (lane == 0) red[warp] = m;
    __syncthreads();
    m = red[lane & 7];
#pragma unroll
    for (int o = 4; o > 0; o >>= 1)
        m = fmaxf(m, __shfl_xor_sync(0xFFFFFFFF, m, o));

    float e0 = __expf(v.x - m), e1 = __expf(v.y - m);
    float e2 = __expf(v.z - m), e3 = __expf(v.w - m);
    float s = e0 + e1 + e2 + e3;
#pragma unroll
    for (int o = 16; o > 0; o >>= 1)
        s += __shfl_xor_sync(0xFFFFFFFF, s, o);
    __syncthreads();
    if (lane == 0) red[warp] = s;
    __syncthreads();
    s = red[lane & 7];
#pragma unroll
    for (int o = 4; o > 0; o >>= 1)
        s += __shfl_xor_sync(0xFFFFFFFF, s, o);
    float inv = 1.0f / s;

    uint2 pk;
    reinterpret_cast<__nv_bfloat162*>(&pk)[0] =
        __nv_bfloat162(__float2bfloat16(e0 * inv), __float2bfloat16(e1 * inv));
    reinterpret_cast<__nv_bfloat162*>(&pk)[1] =
        __nv_bfloat162(__float2bfloat16(e2 * inv), __float2bfloat16(e3 * inv));
    reinterpret_cast<uint2*>(g_beta + row * N_)[tid] = pk;
}

// ---------------------------------------------------------------------------
// Kernel 4: bf16 HMMA GEMM  o[b] = beta[b] @ h_fl[b]  (M=1024, N=768, K=1024)
// CTA tile 128x128x32, 8 warps (4m x 2n), warp tile 32x64 via m16n8k16.
// 3-stage cp.async pipeline (proven round-3 config, ~120 regs, no spill).
// Epilogue fuses hw_recover + gamma*o + x.
// ---------------------------------------------------------------------------
constexpr int BK_    = 32;
constexpr int NK_    = N_ / BK_;   // 32 k-chunks
constexpr int STAGE_ = 16384;      // 8KB A + 8KB B per stage
constexpr int STGS_  = 3;

__global__ __launch_bounds__(256) void k_o_mma(
    const float* __restrict__ x, const float* __restrict__ gammaP,
    float* __restrict__ out)
{
    __shared__ __align__(1024) char smem[STGS_ * STAGE_];
    const uint32_t sbase = smem_u32(smem);

    const int tid  = threadIdx.x;
    const int wid  = tid >> 5;
    const int lane = tid & 31;
    const int wm   = wid & 3;
    const int wn   = wid >> 2;
    const int b     = blockIdx.z;
    const int mBase = blockIdx.y * 128;
    const int cBase = blockIdx.x * 128;

    const __nv_bfloat16* gA = g_beta + ((size_t)b * N_ + mBase) * N_;
    const __nv_bfloat16* gB = g_hT  + ((size_t)b * HC_ + cBase) * N_;

    const int lr = tid >> 2;
    const int lc = tid & 3;

    auto issue = [&](int slot, int kc) {
        const uint32_t aS = sbase + slot * STAGE_;
        const uint32_t bS = aS + 8192;
        const int kOff = kc * BK_ + lc * 8;
#pragma unroll
        for (int i = 0; i < 2; i++) {
            int r = lr + i * 64;
            CP16(aS + swz(r, lc), gA + (size_t)r * N_ + kOff);
        }
#pragma unroll
        for (int i = 0; i < 2; i++) {
            int r = lr + i * 64;
            CP16(bS + swz(r, lc), gB + (size_t)r * N_ + kOff);
        }
    };

    float acc[2][8][4];
#pragma unroll
    for (int mt = 0; mt < 2; mt++)
#pragma unroll
        for (int nt = 0; nt < 8; nt++)
#pragma unroll
            for (int j = 0; j < 4; j++) acc[mt][nt][j] = 0.f;

    issue(0, 0); CPCOMMIT();
    issue(1, 1); CPCOMMIT();

    for (int kc = 0; kc < NK_; kc++) {
        if (kc + 2 < NK_) {
            issue((kc + 2) % STGS_, kc + 2); CPCOMMIT();
            CPWAIT(2);
        } else {
            CPWAIT(0);
        }
        __syncthreads();

        const uint32_t aS = sbase + (kc % STGS_) * STAGE_;
        const uint32_t bS = aS + 8192;
#pragma unroll
        for (int ks = 0; ks < 2; ks++) {
            uint32_t afr[2][4];
#pragma unroll
            for (int mt = 0; mt < 2; mt++) {
                int row = wm * 32 + mt * 16 + ((lane >> 3) & 1) * 8 + (lane & 7);
                int ch  = ks * 2 + (lane >> 4);
                ldsm_x4(afr[mt][0], afr[mt][1], afr[mt][2], afr[mt][3],
                        aS + swz(row, ch));
            }
            uint32_t bfr[8][2];
#pragma unroll
            for (int p = 0; p < 4; p++) {
                int row = wn * 64 + p * 16 + (lane >> 4) * 8 + (lane & 7);
                int ch  = ks * 2 + ((lane >> 3) & 1);
                uint32_t r0, r1, r2, r3;
                ldsm_x4(r0, r1, r2, r3, bS + swz(row, ch));
                bfr[2 * p][0] = r0; bfr[2 * p][1] = r1;
                bfr[2 * p + 1][0] = r2; bfr[2 * p + 1][1] = r3;
            }
#pragma unroll
            for (int mt = 0; mt < 2; mt++)
#pragma unroll
                for (int nt = 0; nt < 8; nt++)
                    mma_bf16(acc[mt][nt], afr[mt], bfr[nt]);
        }
        __syncthreads();
    }

    const float gamma = __ldg(gammaP);
    const int gr = lane >> 2;
    const int qc = (lane & 3) * 2;
#pragma unroll
    for (int mt = 0; mt < 2; mt++) {
#pragma unroll
        for (int rr = 0; rr < 2; rr++) {
            int m    = mBase + wm * 32 + mt * 16 + rr * 8 + gr;
            int hr   = m >> 8;
            int wpix = m & 255;
#pragma unroll
            for (int nt = 0; nt < 8; nt++) {
                int cg = cBase + wn * 64 + nt * 8 + qc;
                int sg = cg >> 8;
                int ch = cg & 255;
                int hh = sg * HS_ + hr;
                size_t idx = (((size_t)b * H_ + hh) * W_ + wpix) * C_ + ch;
                float2 xv = *reinterpret_cast<const float2*>(x + idx);
                float2 o;
                o.x = fmaf(gamma, acc[mt][nt][rr * 2 + 0], xv.x);
                o.y = fmaf(gamma, acc[mt][nt][rr * 2 + 1], xv.y);
                *reinterpret_cast<float2*>(out + idx) = o;
            }
        }
    }
}

// ---------------------------------------------------------------------------
extern "C" void kernel_launch(void* const* d_in, const int* in_sizes, int n_in,
                              void* d_out, int out_size)
{
    const float* x     = (const float*)d_in[0];
    const float* Wf    = (const float*)d_in[1];
    const float* Wg    = (const float*)d_in[2];
    const float* Wh    = (const float*)d_in[3];
    const float* gamma = (const float*)d_in[4];
    float* out = (float*)d_out;

    static bool attrSet = false;
    if (!attrSet) {
        cudaFuncSetAttribute(k_proj_mma, cudaFuncAttributeMaxDynamicSharedMemorySize,
                             PJ_STGS * PJ_STAGE);
        cudaFuncSetAttribute(k_score_mma, cudaFuncAttributeMaxDynamicSharedMemorySize,
                             4 * SC_BUF);
        attrSet = true;
    }

    k_split_x    <<<P_ * C_ / 4 / 256, 256>>>(x);
    k_split_w    <<<320, 256>>>(Wf, Wg, Wh);
    k_proj_mma   <<<dim3(5, P_ / 128), 256, PJ_STGS * PJ_STAGE>>>();
    k_score_mma  <<<dim3(N_ / 128, N_ / 128, B_), 256, 4 * SC_BUF>>>();
    k_softmax    <<<dim3(B_ * N_), 256>>>();
    k_o_mma      <<<dim3(HC_ / 128, N_ / 128, B_), 256>>>(x, gamma, out);
}

// round 7
// speedup vs baseline: 1.9895x; 1.1148x over previous
#include <cuda_runtime.h>
#include <cuda_bf16.h>
#include <cstdint>

// Problem constants
constexpr int B_  = 32;
constexpr int H_  = 12;
constexpr int W_  = 256;
constexpr int C_  = 256;
constexpr int HS_ = 4;            // H / SPLIT
constexpr int N_  = HS_ * W_;     // 1024 flattened spatial
constexpr int FC_ = 96;           // SPLIT * Cf
constexpr int HC_ = 768;          // SPLIT * C
constexpr int P_  = B_ * H_ * W_; // 98304 pixels

// Scratch (device globals)
__device__ __nv_bfloat16 g_xhi[(size_t)P_ * C_];        // 50 MB
__device__ __nv_bfloat16 g_xlo[(size_t)P_ * C_];        // 50 MB
__device__ __nv_bfloat16 g_Wthi[320 * 256];             // [j][k] transposed concat
__device__ __nv_bfloat16 g_Wtlo[320 * 256];
__device__ __nv_bfloat16 g_fhi[(size_t)B_ * N_ * FC_];  // 6.3 MB each
__device__ __nv_bfloat16 g_flo[(size_t)B_ * N_ * FC_];
__device__ __nv_bfloat16 g_ghi[(size_t)B_ * N_ * FC_];
__device__ __nv_bfloat16 g_glo[(size_t)B_ * N_ * FC_];
__device__ float g_s[(size_t)B_ * N_ * N_];             // 134 MB
__device__ __nv_bfloat16 g_beta[(size_t)B_ * N_ * N_];  // 64 MB  [b][n][m]
__device__ __nv_bfloat16 g_hT[(size_t)B_ * HC_ * N_];   // 48 MB  [b][c][n]

// ============================ PTX helpers ==================================
__device__ __forceinline__ uint32_t smem_u32(const void* p) {
    uint32_t a;
    asm("{ .reg .u64 t; cvta.to.shared.u64 t, %1; cvt.u32.u64 %0, t; }"
        : "=r"(a) : "l"(p));
    return a;
}
#define CP16(s, g) \
    asm volatile("cp.async.cg.shared.global [%0], [%1], 16;" \
        :: "r"(s), "l"(g) : "memory")
#define CPCOMMIT() asm volatile("cp.async.commit_group;" ::: "memory")
#define CPWAIT(n)  asm volatile("cp.async.wait_group %0;" :: "n"(n) : "memory")

__device__ __forceinline__ void ldsm_x4(uint32_t& r0, uint32_t& r1,
                                        uint32_t& r2, uint32_t& r3, uint32_t addr) {
    asm volatile("ldmatrix.sync.aligned.m8n8.x4.shared.b16 {%0,%1,%2,%3}, [%4];"
        : "=r"(r0), "=r"(r1), "=r"(r2), "=r"(r3) : "r"(addr));
}
__device__ __forceinline__ void mma_bf16(float* c, const uint32_t* a, const uint32_t* b) {
    asm volatile("mma.sync.aligned.m16n8k16.row.col.f32.bf16.bf16.f32 "
        "{%0,%1,%2,%3}, {%4,%5,%6,%7}, {%8,%9}, {%0,%1,%2,%3};"
        : "+f"(c[0]), "+f"(c[1]), "+f"(c[2]), "+f"(c[3])
        : "r"(a[0]), "r"(a[1]), "r"(a[2]), "r"(a[3]), "r"(b[0]), "r"(b[1]));
}
// smem tile: 64B rows (32 bf16), 4x16B chunks/row, XOR swizzle for ldmatrix
__device__ __forceinline__ uint32_t swz(int r, int c) {
    return (uint32_t)(r * 64 + ((c ^ ((r >> 1) & 3)) << 4));
}
__device__ __forceinline__ void split2(float v, __nv_bfloat16& hi, __nv_bfloat16& lo) {
    hi = __float2bfloat16(v);
    lo = __float2bfloat16(v - __bfloat162float(hi));
}

// ---------------------------------------------------------------------------
// Kernel 0a: split x into bf16 hi/lo
// ---------------------------------------------------------------------------
__global__ __launch_bounds__(256) void k_split_x(const float* __restrict__ x)
{
    size_t gid = (size_t)blockIdx.x * 256 + threadIdx.x;   // float4 index
    float4 v = reinterpret_cast<const float4*>(x)[gid];
    __nv_bfloat16 h0, h1, h2, h3, l0, l1, l2, l3;
    split2(v.x, h0, l0); split2(v.y, h1, l1);
    split2(v.z, h2, l2); split2(v.w, h3, l3);
    uint2 hu, lu;
    reinterpret_cast<__nv_bfloat162*>(&hu)[0] = __nv_bfloat162(h0, h1);
    reinterpret_cast<__nv_bfloat162*>(&hu)[1] = __nv_bfloat162(h2, h3);
    reinterpret_cast<__nv_bfloat162*>(&lu)[0] = __nv_bfloat162(l0, l1);
    reinterpret_cast<__nv_bfloat162*>(&lu)[1] = __nv_bfloat162(l2, l3);
    reinterpret_cast<uint2*>(g_xhi)[gid] = hu;
    reinterpret_cast<uint2*>(g_xlo)[gid] = lu;
}

// ---------------------------------------------------------------------------
// Kernel 0b: build transposed split concat weight Wt[j][k], j in [0,320)
// ---------------------------------------------------------------------------
__global__ __launch_bounds__(256) void k_split_w(
    const float* __restrict__ Wf, const float* __restrict__ Wg,
    const float* __restrict__ Wh)
{
    const int j = blockIdx.x;
    const int k = threadIdx.x;
    float v;
    if (j < 256)      v = Wh[k * 256 + j];
    else if (j < 288) v = Wf[k * 32 + (j - 256)];
    else              v = Wg[k * 32 + (j - 288)];
    __nv_bfloat16 hi, lo;
    split2(v, hi, lo);
    g_Wthi[j * 256 + k] = hi;
    g_Wtlo[j * 256 + k] = lo;
}

// ---------------------------------------------------------------------------
// Kernel 1a: h projection, 1-pass bf16 HMMA (h is bf16-stored + gamma-scaled:
// 1-pass error ~0.6% x 3% contribution is within budget).
// Tile 128(p) x 64(c), K=256. 8 warps (4m x 2n).
// Epilogue: transpose in smem -> coalesced g_hT write.
// ---------------------------------------------------------------------------
constexpr int PH_STAGE = 12288;   // Ah 8K + Bh 4K
constexpr int PH_STGS  = 3;
constexpr int TS_ = 136;          // transpose staging row pitch (bf16)

__global__ __launch_bounds__(256) void k_proj_h()
{
    extern __shared__ char smem[];
    const uint32_t sbase = smem_u32(smem);
    const int tid  = threadIdx.x;
    const int wid  = tid >> 5;
    const int lane = tid & 31;
    const int wm   = wid & 3;
    const int wn   = wid >> 2;
    const int cBase = blockIdx.x * 64;     // 0..3 -> channels 0..255
    const int pBase = blockIdx.y * 128;

    const __nv_bfloat16* gAh = g_xhi + (size_t)pBase * 256;
    const __nv_bfloat16* gBh = g_Wthi + (size_t)cBase * 256;

    const int arow = tid >> 2, ac = tid & 3;
    auto issue = [&](int slot, int kc) {
        const uint32_t st = sbase + slot * PH_STAGE;
#pragma unroll
        for (int i = 0; i < 2; i++) {
            int idx = i * 256 + tid;
            int r = idx >> 2, c = idx & 3;
            CP16(st + swz(r, c), gAh + (size_t)r * 256 + kc * 32 + c * 8);
        }
        if (arow < 64)
            CP16(st + 8192 + swz(arow, ac), gBh + (size_t)arow * 256 + kc * 32 + ac * 8);
    };

    float acc[2][4][4];
#pragma unroll
    for (int mt = 0; mt < 2; mt++)
#pragma unroll
        for (int nt = 0; nt < 4; nt++)
#pragma unroll
            for (int j = 0; j < 4; j++) acc[mt][nt][j] = 0.f;

    issue(0, 0); CPCOMMIT();
    issue(1, 1); CPCOMMIT();

    for (int kc = 0; kc < 8; kc++) {
        if (kc + 2 < 8) {
            issue((kc + 2) % PH_STGS, kc + 2); CPCOMMIT();
            CPWAIT(2);
        } else {
            CPWAIT(0);
        }
        __syncthreads();
        const uint32_t st = sbase + (kc % PH_STGS) * PH_STAGE;
#pragma unroll
        for (int ks = 0; ks < 2; ks++) {
            uint32_t ah[2][4];
#pragma unroll
            for (int mt = 0; mt < 2; mt++) {
                int row = wm * 32 + mt * 16 + ((lane >> 3) & 1) * 8 + (lane & 7);
                int ch  = ks * 2 + (lane >> 4);
                ldsm_x4(ah[mt][0], ah[mt][1], ah[mt][2], ah[mt][3], st + swz(row, ch));
            }
            uint32_t bh[4][2];
#pragma unroll
            for (int p = 0; p < 2; p++) {
                int row = wn * 32 + p * 16 + (lane >> 4) * 8 + (lane & 7);
                int ch  = ks * 2 + ((lane >> 3) & 1);
                uint32_t r0, r1, r2, r3;
                ldsm_x4(r0, r1, r2, r3, st + 8192 + swz(row, ch));
                bh[2 * p][0] = r0; bh[2 * p][1] = r1;
                bh[2 * p + 1][0] = r2; bh[2 * p + 1][1] = r3;
            }
#pragma unroll
            for (int mt = 0; mt < 2; mt++)
#pragma unroll
                for (int nt = 0; nt < 4; nt++)
                    mma_bf16(acc[mt][nt], ah[mt], bh[nt]);
        }
        __syncthreads();
    }

    // Geometry: 128 consecutive pixels = fixed (b, h), 128 consecutive w.
    const int gr = lane >> 2;
    const int qc = (lane & 3) * 2;
    const int bb  = pBase / (H_ * W_);
    const int rem = pBase - bb * (H_ * W_);
    const int hpx = rem >> 8;
    const int w0  = rem & 255;
    const int sg  = hpx >> 2;
    const int hr  = hpx & 3;
    const int n0  = hr * W_ + w0;

    // Stage transposed [c=64][n=128] in smem, write g_hT coalesced
    __nv_bfloat16* ts = reinterpret_cast<__nv_bfloat16*>(smem);
#pragma unroll
    for (int mt = 0; mt < 2; mt++)
#pragma unroll
        for (int rr = 0; rr < 2; rr++) {
            int nl = wm * 32 + mt * 16 + rr * 8 + gr;
#pragma unroll
            for (int nt = 0; nt < 4; nt++) {
                int cl = wn * 32 + nt * 8 + qc;
                ts[cl * TS_ + nl]       = __float2bfloat16(acc[mt][nt][rr * 2 + 0]);
                ts[(cl + 1) * TS_ + nl] = __float2bfloat16(acc[mt][nt][rr * 2 + 1]);
            }
        }
    __syncthreads();
    const size_t hTrow0 = ((size_t)bb * HC_ + sg * 256 + cBase) * N_ + n0;
#pragma unroll
    for (int i = 0; i < 4; i++) {
        int idx = i * 256 + tid;
        int r = idx >> 4, u = idx & 15;
        uint4 v = *reinterpret_cast<const uint4*>(&ts[r * TS_ + u * 8]);
        *reinterpret_cast<uint4*>(&g_hT[hTrow0 + (size_t)r * N_ + u * 8]) = v;
    }
}

// ---------------------------------------------------------------------------
// Kernel 1b: f/g projection via 3-pass bf16 HMMA (logits precision-critical).
// Tile 128(p) x 64(c: f 32 + g 32), K=256. 8 warps (4m x 2n).
// ---------------------------------------------------------------------------
constexpr int PJ_STAGE = 24576;   // Ah 8K + Al 8K + Bh 4K + Bl 4K
constexpr int PJ_STGS  = 3;

__global__ __launch_bounds__(256) void k_proj_fg()
{
    extern __shared__ char smem[];
    const uint32_t sbase = smem_u32(smem);
    const int tid  = threadIdx.x;
    const int wid  = tid >> 5;
    const int lane = tid & 31;
    const int wm   = wid & 3;
    const int wn   = wid >> 2;
    const int cBase = 256;                 // f/g columns 256..319
    const int pBase = blockIdx.x * 128;

    const __nv_bfloat16* gAh = g_xhi + (size_t)pBase * 256;
    const __nv_bfloat16* gAl = g_xlo + (size_t)pBase * 256;
    const __nv_bfloat16* gBh = g_Wthi + (size_t)cBase * 256;
    const __nv_bfloat16* gBl = g_Wtlo + (size_t)cBase * 256;

    const int arow = tid >> 2, ac = tid & 3;
    auto issue = [&](int slot, int kc) {
        const uint32_t st = sbase + slot * PJ_STAGE;
        const int kOff = kc * 32 + ac * 8;
#pragma unroll
        for (int i = 0; i < 2; i++) {
            int idx = i * 256 + tid;
            int r = idx >> 2, c = idx & 3;
            int ko = kc * 32 + c * 8;
            CP16(st + swz(r, c), gAh + (size_t)r * 256 + ko);
            CP16(st + 8192 + swz(r, c), gAl + (size_t)r * 256 + ko);
        }
        if (arow < 64) {
            CP16(st + 16384 + swz(arow, ac), gBh + (size_t)arow * 256 + kOff);
            CP16(st + 20480 + swz(arow, ac), gBl + (size_t)arow * 256 + kOff);
        }
    };

    float acc[2][4][4];
#pragma unroll
    for (int mt = 0; mt < 2; mt++)
#pragma unroll
        for (int nt = 0; nt < 4; nt++)
#pragma unroll
            for (int j = 0; j < 4; j++) acc[mt][nt][j] = 0.f;

    issue(0, 0); CPCOMMIT();
    issue(1, 1); CPCOMMIT();

    for (int kc = 0; kc < 8; kc++) {
        if (kc + 2 < 8) {
            issue((kc + 2) % PJ_STGS, kc + 2); CPCOMMIT();
            CPWAIT(2);
        } else {
            CPWAIT(0);
        }
        __syncthreads();
        const uint32_t st = sbase + (kc % PJ_STGS) * PJ_STAGE;
#pragma unroll
        for (int ks = 0; ks < 2; ks++) {
            uint32_t ah[2][4], al[2][4];
#pragma unroll
            for (int mt = 0; mt < 2; mt++) {
                int row = wm * 32 + mt * 16 + ((lane >> 3) & 1) * 8 + (lane & 7);
                int ch  = ks * 2 + (lane >> 4);
                ldsm_x4(ah[mt][0], ah[mt][1], ah[mt][2], ah[mt][3], st + swz(row, ch));
                ldsm_x4(al[mt][0], al[mt][1], al[mt][2], al[mt][3], st + 8192 + swz(row, ch));
            }
            uint32_t bh[4][2], bl[4][2];
#pragma unroll
            for (int p = 0; p < 2; p++) {
                int row = wn * 32 + p * 16 + (lane >> 4) * 8 + (lane & 7);
                int ch  = ks * 2 + ((lane >> 3) & 1);
                uint32_t r0, r1, r2, r3;
                ldsm_x4(r0, r1, r2, r3, st + 16384 + swz(row, ch));
                bh[2 * p][0] = r0; bh[2 * p][1] = r1;
                bh[2 * p + 1][0] = r2; bh[2 * p + 1][1] = r3;
                ldsm_x4(r0, r1, r2, r3, st + 20480 + swz(row, ch));
                bl[2 * p][0] = r0; bl[2 * p][1] = r1;
                bl[2 * p + 1][0] = r2; bl[2 * p + 1][1] = r3;
            }
#pragma unroll
            for (int mt = 0; mt < 2; mt++)
#pragma unroll
                for (int nt = 0; nt < 4; nt++) {
                    mma_bf16(acc[mt][nt], ah[mt], bh[nt]);
                    mma_bf16(acc[mt][nt], ah[mt], bl[nt]);
                    mma_bf16(acc[mt][nt], al[mt], bh[nt]);
                }
        }
        __syncthreads();
    }

    const int gr = lane >> 2;
    const int qc = (lane & 3) * 2;
    const int bb  = pBase / (H_ * W_);
    const int rem = pBase - bb * (H_ * W_);
    const int hpx = rem >> 8;
    const int w0  = rem & 255;
    const int sg  = hpx >> 2;
    const int hr  = hpx & 3;
    const int n0  = hr * W_ + w0;

#pragma unroll
    for (int mt = 0; mt < 2; mt++)
#pragma unroll
        for (int rr = 0; rr < 2; rr++) {
            int nl = wm * 32 + mt * 16 + rr * 8 + gr;
            int n  = n0 + nl;
            size_t base = ((size_t)bb * N_ + n) * FC_ + sg * 32;
#pragma unroll
            for (int nt = 0; nt < 4; nt++) {
                int j = cBase + wn * 32 + nt * 8 + qc;   // 256..319
                float v0 = acc[mt][nt][rr * 2 + 0];
                float v1 = acc[mt][nt][rr * 2 + 1];
                __nv_bfloat16 h0, h1, l0, l1;
                split2(v0, h0, l0); split2(v1, h1, l1);
                __nv_bfloat162 hv(h0, h1), lv(l0, l1);
                if (j < 288) {
                    size_t idx = base + (j - 256);
                    *reinterpret_cast<__nv_bfloat162*>(&g_fhi[idx]) = hv;
                    *reinterpret_cast<__nv_bfloat162*>(&g_flo[idx]) = lv;
                } else {
                    size_t idx = base + (j - 288);
                    *reinterpret_cast<__nv_bfloat162*>(&g_ghi[idx]) = hv;
                    *reinterpret_cast<__nv_bfloat162*>(&g_glo[idx]) = lv;
                }
            }
        }
}

// ---------------------------------------------------------------------------
// Kernel 2: s[b] = g_fl[b] @ f_fl[b]^T via 3-pass bf16 HMMA.
// Tile 128x128, K=96 one-shot (3 subtiles of 32). 8 warps (4m x 2n).
// ---------------------------------------------------------------------------
constexpr int SC_BUF = 24576;   // one operand buffer: 3 subtiles x 8KB

__global__ __launch_bounds__(256) void k_score_mma()
{
    extern __shared__ char smem[];
    const uint32_t sbase = smem_u32(smem);
    const int tid  = threadIdx.x;
    const int wid  = tid >> 5;
    const int lane = tid & 31;
    const int wm   = wid & 3;
    const int wn   = wid >> 2;
    const int b     = blockIdx.z;
    const int mBase = blockIdx.x * 128;   // cols of s (f index)
    const int nBase = blockIdx.y * 128;   // rows of s (g index)

    const __nv_bfloat16* srcs[4] = {
        g_ghi + ((size_t)b * N_ + nBase) * FC_,
        g_glo + ((size_t)b * N_ + nBase) * FC_,
        g_fhi + ((size_t)b * N_ + mBase) * FC_,
        g_flo + ((size_t)b * N_ + mBase) * FC_ };

#pragma unroll
    for (int bf = 0; bf < 4; bf++) {
        const __nv_bfloat16* src = srcs[bf];
        const uint32_t bufS = sbase + bf * SC_BUF;
#pragma unroll
        for (int t = 0; t < 3; t++)
#pragma unroll
            for (int i = 0; i < 2; i++) {
                int idx = i * 256 + tid;
                int r = idx >> 2, c = idx & 3;
                CP16(bufS + t * 8192 + swz(r, c),
                     src + (size_t)r * FC_ + t * 32 + c * 8);
            }
    }
    CPCOMMIT(); CPWAIT(0);
    __syncthreads();

    float acc[2][8][4];
#pragma unroll
    for (int mt = 0; mt < 2; mt++)
#pragma unroll
        for (int nt = 0; nt < 8; nt++)
#pragma unroll
            for (int j = 0; j < 4; j++) acc[mt][nt][j] = 0.f;

    const uint32_t AhS = sbase, AlS = sbase + SC_BUF;
    const uint32_t BhS = sbase + 2 * SC_BUF, BlS = sbase + 3 * SC_BUF;

#pragma unroll
    for (int t = 0; t < 3; t++) {
#pragma unroll
        for (int ks = 0; ks < 2; ks++) {
            uint32_t ah[2][4], al[2][4];
#pragma unroll
            for (int mt = 0; mt < 2; mt++) {
                int row = wm * 32 + mt * 16 + ((lane >> 3) & 1) * 8 + (lane & 7);
                int ch  = ks * 2 + (lane >> 4);
                ldsm_x4(ah[mt][0], ah[mt][1], ah[mt][2], ah[mt][3],
                        AhS + t * 8192 + swz(row, ch));
                ldsm_x4(al[mt][0], al[mt][1], al[mt][2], al[mt][3],
                        AlS + t * 8192 + swz(row, ch));
            }
            uint32_t bh[8][2], bl[8][2];
#pragma unroll
            for (int p = 0; p < 4; p++) {
                int row = wn * 64 + p * 16 + (lane >> 4) * 8 + (lane & 7);
                int ch  = ks * 2 + ((lane >> 3) & 1);
                uint32_t r0, r1, r2, r3;
                ldsm_x4(r0, r1, r2, r3, BhS + t * 8192 + swz(row, ch));
                bh[2 * p][0] = r0; bh[2 * p][1] = r1;
                bh[2 * p + 1][0] = r2; bh[2 * p + 1][1] = r3;
                ldsm_x4(r0, r1, r2, r3, BlS + t * 8192 + swz(row, ch));
                bl[2 * p][0] = r0; bl[2 * p][1] = r1;
                bl[2 * p + 1][0] = r2; bl[2 * p + 1][1] = r3;
            }
#pragma unroll
            for (int mt = 0; mt < 2; mt++)
#pragma unroll
                for (int nt = 0; nt < 8; nt++) {
                    mma_bf16(acc[mt][nt], ah[mt], bh[nt]);
                    mma_bf16(acc[mt][nt], ah[mt], bl[nt]);
                    mma_bf16(acc[mt][nt], al[mt], bh[nt]);
                }
        }
    }

    float* sp = g_s + (size_t)b * N_ * N_;
    const int gr = lane >> 2;
    const int qc = (lane & 3) * 2;
#pragma unroll
    for (int mt = 0; mt < 2; mt++)
#pragma unroll
        for (int rr = 0; rr < 2; rr++) {
            int n = nBase + wm * 32 + mt * 16 + rr * 8 + gr;
#pragma unroll
            for (int nt = 0; nt < 8; nt++) {
                int m = mBase + wn * 64 + nt * 8 + qc;
                float2 v = make_float2(acc[mt][nt][rr * 2], acc[mt][nt][rr * 2 + 1]);
                *reinterpret_cast<float2*>(&sp[(size_t)n * N_ + m]) = v;
            }
        }
}

// ---------------------------------------------------------------------------
// Kernel 3: row softmax (float4 + shuffle reductions); writes bf16 beta
// ---------------------------------------------------------------------------
__global__ __launch_bounds__(256) void k_softmax()
{
    const size_t row = blockIdx.x;
    const float4* sp4 = reinterpret_cast<const float4*>(g_s + row * N_);
    const int tid = threadIdx.x;
    const int lane = tid & 31, warp = tid >> 5;
    __shared__ float red[8];

    float4 v = sp4[tid];
    float m = fmaxf(fmaxf(v.x, v.y), fmaxf(v.z, v.w));
#pragma unroll
    for (int o = 16; o > 0; o >>= 1)
        m = fmaxf(m, __shfl_xor_sync(0xFFFFFFFF, m, o));
    if (lane == 0) red[warp] = m;
    __syncthreads();
    m = red[lane & 7];
#pragma unroll
    for (int o = 4; o > 0; o >>= 1)
        m = fmaxf(m, __shfl_xor_sync(0xFFFFFFFF, m, o));

    float e0 = __expf(v.x - m), e1 = __expf(v.y - m);
    float e2 = __expf(v.z - m), e3 = __expf(v.w - m);
    float s = e0 + e1 + e2 + e3;
#pragma unroll
    for (int o = 16; o > 0; o >>= 1)
        s += __shfl_xor_sync(0xFFFFFFFF, s, o);
    __syncthreads();
    if (lane == 0) red[warp] = s;
    __syncthreads();
    s = red[lane & 7];
#pragma unroll
    for (int o = 4; o > 0; o >>= 1)
        s += __shfl_xor_sync(0xFFFFFFFF, s, o);
    float inv = 1.0f / s;

    uint2 pk;
    reinterpret_cast<__nv_bfloat162*>(&pk)[0] =
        __nv_bfloat162(__float2bfloat16(e0 * inv), __float2bfloat16(e1 * inv));
    reinterpret_cast<__nv_bfloat162*>(&pk)[1] =
        __nv_bfloat162(__float2bfloat16(e2 * inv), __float2bfloat16(e3 * inv));
    reinterpret_cast<uint2*>(g_beta + row * N_)[tid] = pk;
}

// ---------------------------------------------------------------------------
// Kernel 4: bf16 HMMA GEMM  o[b] = beta[b] @ h_fl[b]  (M=1024, N=768, K=1024)
// CTA tile 128x128x32, 8 warps (4m x 2n). 4-stage cp.async pipeline.
// Epilogue fuses hw_recover + gamma*o + x.
// ---------------------------------------------------------------------------
constexpr int BK_    = 32;
constexpr int NK_    = N_ / BK_;   // 32 k-chunks
constexpr int STAGE_ = 16384;      // 8KB A + 8KB B per stage
constexpr int STGS_  = 4;

__global__ __launch_bounds__(256) void k_o_mma(
    const float* __restrict__ x, const float* __restrict__ gammaP,
    float* __restrict__ out)
{
    extern __shared__ char smem[];
    const uint32_t sbase = smem_u32(smem);

    const int tid  = threadIdx.x;
    const int wid  = tid >> 5;
    const int lane = tid & 31;
    const int wm   = wid & 3;
    const int wn   = wid >> 2;
    const int b     = blockIdx.z;
    const int mBase = blockIdx.y * 128;
    const int cBase = blockIdx.x * 128;

    const __nv_bfloat16* gA = g_beta + ((size_t)b * N_ + mBase) * N_;
    const __nv_bfloat16* gB = g_hT  + ((size_t)b * HC_ + cBase) * N_;

    const int lr = tid >> 2;
    const int lc = tid & 3;

    auto issue = [&](int slot, int kc) {
        const uint32_t aS = sbase + slot * STAGE_;
        const uint32_t bS = aS + 8192;
        const int kOff = kc * BK_ + lc * 8;
#pragma unroll
        for (int i = 0; i < 2; i++) {
            int r = lr + i * 64;
            CP16(aS + swz(r, lc), gA + (size_t)r * N_ + kOff);
        }
#pragma unroll
        for (int i = 0; i < 2; i++) {
            int r = lr + i * 64;
            CP16(bS + swz(r, lc), gB + (size_t)r * N_ + kOff);
        }
    };

    float acc[2][8][4];
#pragma unroll
    for (int mt = 0; mt < 2; mt++)
#pragma unroll
        for (int nt = 0; nt < 8; nt++)
#pragma unroll
            for (int j = 0; j < 4; j++) acc[mt][nt][j] = 0.f;

    issue(0, 0); CPCOMMIT();
    issue(1, 1); CPCOMMIT();
    issue(2, 2); CPCOMMIT();

    for (int kc = 0; kc < NK_; kc++) {
        if (kc + 3 < NK_) {
            issue((kc + 3) % STGS_, kc + 3); CPCOMMIT();
            CPWAIT(3);
        } else {
            CPWAIT(0);
        }
        __syncthreads();

        const uint32_t aS = sbase + (kc % STGS_) * STAGE_;
        const uint32_t bS = aS + 8192;
#pragma unroll
        for (int ks = 0; ks < 2; ks++) {
            uint32_t afr[2][4];
#pragma unroll
            for (int mt = 0; mt < 2; mt++) {
                int row = wm * 32 + mt * 16 + ((lane >> 3) & 1) * 8 + (lane & 7);
                int ch  = ks * 2 + (lane >> 4);
                ldsm_x4(afr[mt][0], afr[mt][1], afr[mt][2], afr[mt][3],
                        aS + swz(row, ch));
            }
            uint32_t bfr[8][2];
#pragma unroll
            for (int p = 0; p < 4; p++) {
                int row = wn * 64 + p * 16 + (lane >> 4) * 8 + (lane & 7);
                int ch  = ks * 2 + ((lane >> 3) & 1);
                uint32_t r0, r1, r2, r3;
                ldsm_x4(r0, r1, r2, r3, bS + swz(row, ch));
                bfr[2 * p][0] = r0; bfr[2 * p][1] = r1;
                bfr[2 * p + 1][0] = r2; bfr[2 * p + 1][1] = r3;
            }
#pragma unroll
            for (int mt = 0; mt < 2; mt++)
#pragma unroll
                for (int nt = 0; nt < 8; nt++)
                    mma_bf16(acc[mt][nt], afr[mt], bfr[nt]);
        }
        __syncthreads();
    }

    const float gamma = __ldg(gammaP);
    const int gr = lane >> 2;
    const int qc = (lane & 3) * 2;
#pragma unroll
    for (int mt = 0; mt < 2; mt++) {
#pragma unroll
        for (int rr = 0; rr < 2; rr++) {
            int m    = mBase + wm * 32 + mt * 16 + rr * 8 + gr;
            int hr   = m >> 8;
            int wpix = m & 255;
#pragma unroll
            for (int nt = 0; nt < 8; nt++) {
                int cg = cBase + wn * 64 + nt * 8 + qc;
                int sg = cg >> 8;
                int ch = cg & 255;
                int hh = sg * HS_ + hr;
                size_t idx = (((size_t)b * H_ + hh) * W_ + wpix) * C_ + ch;
                float2 xv = *reinterpret_cast<const float2*>(x + idx);
                float2 o;
                o.x = fmaf(gamma, acc[mt][nt][rr * 2 + 0], xv.x);
                o.y = fmaf(gamma, acc[mt][nt][rr * 2 + 1], xv.y);
                *reinterpret_cast<float2*>(out + idx) = o;
            }
        }
    }
}

// ---------------------------------------------------------------------------
extern "C" void kernel_launch(void* const* d_in, const int* in_sizes, int n_in,
                              void* d_out, int out_size)
{
    const float* x     = (const float*)d_in[0];
    const float* Wf    = (const float*)d_in[1];
    const float* Wg    = (const float*)d_in[2];
    const float* Wh    = (const float*)d_in[3];
    const float* gamma = (const float*)d_in[4];
    float* out = (float*)d_out;

    static bool attrSet = false;
    if (!attrSet) {
        cudaFuncSetAttribute(k_proj_h, cudaFuncAttributeMaxDynamicSharedMemorySize,
                             PH_STGS * PH_STAGE);
        cudaFuncSetAttribute(k_proj_fg, cudaFuncAttributeMaxDynamicSharedMemorySize,
                             PJ_STGS * PJ_STAGE);
        cudaFuncSetAttribute(k_score_mma, cudaFuncAttributeMaxDynamicSharedMemorySize,
                             4 * SC_BUF);
        cudaFuncSetAttribute(k_o_mma, cudaFuncAttributeMaxDynamicSharedMemorySize,
                             STGS_ * STAGE_);
        attrSet = true;
    }

    k_split_x  <<<P_ * C_ / 4 / 256, 256>>>(x);
    k_split_w  <<<320, 256>>>(Wf, Wg, Wh);
    k_proj_h   <<<dim3(4, P_ / 128), 256, PH_STGS * PH_STAGE>>>();
    k_proj_fg  <<<P_ / 128, 256, PJ_STGS * PJ_STAGE>>>();
    k_score_mma<<<dim3(N_ / 128, N_ / 128, B_), 256, 4 * SC_BUF>>>();
    k_softmax  <<<dim3(B_ * N_), 256>>>();
    k_o_mma    <<<dim3(HC_ / 128, N_ / 128, B_), 256,
                  STGS_ * STAGE_>>>(x, gamma, out);
}